// round 5
// baseline (speedup 1.0000x reference)
#include <cuda_runtime.h>
#include <cuda_fp16.h>
#include <math.h>
#include <stdint.h>

// MoE: B=8, N=1024, E=1024, H=1536, X=8, K=2
#define B_  8
#define N_  1024
#define T_  (B_*N_)      // 8192 tokens
#define E_  1024
#define H_  1536
#define X_  8
#define K_  2
#define TS_ (T_*K_)      // 16384 (token, slot) pairs

// ---- scratch (allocation-free: __device__ globals) ----
__device__ int    g_count[X_];
__device__ int    g_slots[X_ * T_];                      // slot id = t*K + k
__device__ __half g_xh[(size_t)T_ * E_];                 // x in fp16
__device__ __half g_W1T[(size_t)X_ * H_ * E_];           // [x][h][e] fp16 (B n-major)
__device__ __half g_W2T[(size_t)X_ * E_ * H_];           // [x][e][h] fp16
__device__ __half g_hh[(size_t)TS_ * H_];                // post-GELU hidden (fp16)
__device__ float  g_y[(size_t)TS_ * E_];                 // expert output (fp32)

// ============================ helpers =======================================
__device__ __forceinline__ uint32_t smem_u32(const void* p) {
    uint32_t a;
    asm("{ .reg .u64 t; cvta.to.shared.u64 t, %1; cvt.u32.u64 %0, t; }" : "=r"(a) : "l"(p));
    return a;
}
__device__ __forceinline__ void cp16z(uint32_t dst, const void* src, uint32_t sz) {
    asm volatile("cp.async.cg.shared.global [%0], [%1], 16, %2;"
                 :: "r"(dst), "l"(src), "r"(sz) : "memory");
}
__device__ __forceinline__ void cp16(uint32_t dst, const void* src) {
    asm volatile("cp.async.cg.shared.global [%0], [%1], 16;"
                 :: "r"(dst), "l"(src) : "memory");
}
#define CP_COMMIT() asm volatile("cp.async.commit_group;" ::: "memory")
#define CP_WAIT0()  asm volatile("cp.async.wait_group 0;" ::: "memory")

__device__ __forceinline__ void ldm_x4(uint32_t* r, uint32_t addr) {
    asm volatile("ldmatrix.sync.aligned.m8n8.x4.shared.b16 {%0,%1,%2,%3}, [%4];"
                 : "=r"(r[0]), "=r"(r[1]), "=r"(r[2]), "=r"(r[3]) : "r"(addr));
}
__device__ __forceinline__ void mma_f16(float* c, const uint32_t* a, const uint32_t* b) {
    asm volatile("mma.sync.aligned.m16n8k16.row.col.f32.f16.f16.f32 "
                 "{%0,%1,%2,%3}, {%4,%5,%6,%7}, {%8,%9}, {%0,%1,%2,%3};"
                 : "+f"(c[0]), "+f"(c[1]), "+f"(c[2]), "+f"(c[3])
                 : "r"(a[0]), "r"(a[1]), "r"(a[2]), "r"(a[3]), "r"(b[0]), "r"(b[1]));
}

__device__ __forceinline__ float gelu_erf(float v) {
    return 0.5f * v * (1.0f + erff(v * 0.70710678118654752f));
}

// ---------------------------------------------------------------------------
__global__ void reset_kernel() {
    if (threadIdx.x < X_) g_count[threadIdx.x] = 0;
}

// ---------------------------------------------------------------------------
// Router: one warp per token (top-2 of logits == top-2 of softmax).
__global__ void router_kernel(const float* __restrict__ x,
                              const float* __restrict__ Wr,
                              const float* __restrict__ br,
                              float* __restrict__ out_idx) {
    int gwarp = (blockIdx.x * blockDim.x + threadIdx.x) >> 5;
    int lane  = threadIdx.x & 31;
    if (gwarp >= T_) return;
    const float* xr = x + (size_t)gwarp * E_;

    float acc[X_];
#pragma unroll
    for (int j = 0; j < X_; j++) acc[j] = 0.f;
    for (int e = lane; e < E_; e += 32) {
        float xv = xr[e];
        const float4* w4 = (const float4*)(Wr + (size_t)e * X_);
        float4 w0 = w4[0], w1 = w4[1];
        acc[0] += xv * w0.x; acc[1] += xv * w0.y;
        acc[2] += xv * w0.z; acc[3] += xv * w0.w;
        acc[4] += xv * w1.x; acc[5] += xv * w1.y;
        acc[6] += xv * w1.z; acc[7] += xv * w1.w;
    }
#pragma unroll
    for (int j = 0; j < X_; j++)
#pragma unroll
        for (int off = 16; off > 0; off >>= 1)
            acc[j] += __shfl_down_sync(0xffffffffu, acc[j], off);

    if (lane == 0) {
        float v0 = -3.0e38f, v1 = -3.0e38f;
        int   i0 = 0,        i1 = 0;
#pragma unroll
        for (int j = 0; j < X_; j++) {
            float v = acc[j] + br[j];
            if (v > v0)      { v1 = v0; i1 = i0; v0 = v; i0 = j; }
            else if (v > v1) { v1 = v;  i1 = j; }
        }
        if (out_idx) {
            out_idx[gwarp * K_ + 0] = (float)i0;
            out_idx[gwarp * K_ + 1] = (float)i1;
        }
        int p0 = atomicAdd(&g_count[i0], 1);
        g_slots[i0 * T_ + p0] = gwarp * K_ + 0;
        int p1 = atomicAdd(&g_count[i1], 1);
        g_slots[i1 * T_ + p1] = gwarp * K_ + 1;
    }
}

// ---------------------------------------------------------------------------
// x fp32 -> fp16
__global__ void cvt_x_kernel(const float* __restrict__ x) {
    int i = blockIdx.x * 256 + threadIdx.x;             // over T_*E_/4
    float4 v = ((const float4*)x)[i];
    __half2 h0 = __floats2half2_rn(v.x, v.y);
    __half2 h1 = __floats2half2_rn(v.z, v.w);
    ((__half2*)g_xh)[2 * i]     = h0;
    ((__half2*)g_xh)[2 * i + 1] = h1;
}

// in [R][C] fp32 -> out [C][R] fp16 (transpose + convert), batched over z
__global__ void transpose_cvt_kernel(const float* __restrict__ in,
                                     __half* __restrict__ out, int R, int C) {
    __shared__ float t[32][33];
    size_t base = (size_t)blockIdx.z * R * C;
    in  += base; out += base;
    int c0 = blockIdx.x * 32, r0 = blockIdx.y * 32;
#pragma unroll
    for (int j = 0; j < 32; j += 8)
        t[threadIdx.y + j][threadIdx.x] =
            in[(size_t)(r0 + threadIdx.y + j) * C + c0 + threadIdx.x];
    __syncthreads();
#pragma unroll
    for (int j = 0; j < 32; j += 8)
        out[(size_t)(c0 + threadIdx.y + j) * R + r0 + threadIdx.x] =
            __float2half_rn(t[threadIdx.x][threadIdx.y + j]);
}

// ---------------------------------------------------------------------------
// fp16 mma.sync grouped GEMM: 128x128 tile, BK=64 halves, double-buffered
// cp.async, ldmatrix fragment loads. A [m][k], B [n][k], pitch 144 bytes.
// FIRST: C = gelu(xh[token] @ W1T^T + b1) -> g_hh  (KDIM=E_, NDIM=H_)
// else : C =      g_hh[slot] @ W2T^T + b2 -> g_y   (KDIM=H_, NDIM=E_)
#define BKH      64
#define PITCH_B  144                     // bytes per row -> ldmatrix conflict-free
#define OP_BYTES (128 * PITCH_B)         // one operand per stage (18432 B)
#define STAGE_B  (2 * OP_BYTES)          // 36864 B per stage (A+B)
#define GEMM_SMEM (1024 + 2 * STAGE_B)

template<int KDIM, int NDIM, bool FIRST>
__global__ __launch_bounds__(256)
void expert_gemm_h(const __half* __restrict__ WT_all,
                   const float* __restrict__ bias_all) {
    extern __shared__ char smx[];
    int*    sSlot = (int*)smx;                 // 128
    float*  sBias = (float*)(smx + 512);       // 128
    char*   sData = smx + 1024;

    const int z    = blockIdx.z;
    const int cnt  = g_count[z];
    const int row0 = blockIdx.y * 128;
    if (row0 >= cnt) return;
    const int jn0  = blockIdx.x * 128;
    const int tid  = threadIdx.x;
    const int lane = tid & 31;
    const int wid  = tid >> 5;

    if (tid < 128) {
        int r = row0 + tid;
        sSlot[tid] = (r < cnt) ? g_slots[z * T_ + r] : -1;
        sBias[tid] = bias_all[(size_t)z * NDIM + jn0 + tid];
    }
    __syncthreads();

    const __half* Abase = FIRST ? g_xh : g_hh;
    const __half* WT    = WT_all + (size_t)z * NDIM * KDIM;

    const uint32_t smb = smem_u32(sData);

    // cp.async mapping: 4 chunks/thread per operand; chunk c=tid*4+j: row=c>>3, col16=c&7
    const __half* aSrc[4]; const __half* bSrc[4];
    uint32_t aSz[4], aDst[4], bDst[4];
#pragma unroll
    for (int j = 0; j < 4; j++) {
        int c = tid * 4 + j;
        int row = c >> 3, col = c & 7;
        int slot = sSlot[row];
        int arow = 0; uint32_t sz = 0;
        if (slot >= 0) { arow = FIRST ? (slot >> 1) : slot; sz = 16; }
        aSrc[j] = Abase + (size_t)arow * KDIM + col * 8;
        aSz[j]  = sz;
        bSrc[j] = WT + (size_t)(jn0 + row) * KDIM + col * 8;
        uint32_t o = (uint32_t)(row * PITCH_B + col * 16);
        aDst[j] = smb + o;
        bDst[j] = smb + OP_BYTES + o;
    }

    constexpr int NC = KDIM / BKH;

    // prologue: chunk 0 -> stage 0
#pragma unroll
    for (int j = 0; j < 4; j++) {
        cp16z(aDst[j], aSrc[j], aSz[j]);
        cp16 (bDst[j], bSrc[j]);
    }
    CP_COMMIT();

    float acc[4][4][4];
#pragma unroll
    for (int mt = 0; mt < 4; mt++)
#pragma unroll
        for (int nt = 0; nt < 4; nt++)
#pragma unroll
            for (int q = 0; q < 4; q++) acc[mt][nt][q] = 0.f;

    const int warp_m = wid & 1;      // 2 warps over M (64 rows each)
    const int warp_n = wid >> 1;     // 4 warps over N (32 cols each)
    const int lr = lane >> 2;        // group 0..7
    const int lc = lane & 3;         // 0..3

    // ldmatrix lane address bases (byte offsets within operand tile)
    // A x4: m = base + (lane&15), k-half offset 8*(lane>>4)
    const uint32_t aLd = (uint32_t)((warp_m * 64 + (lane & 15)) * PITCH_B + (lane >> 4) * 16);
    // B x4 (nt pair): n = base + (lane&7) + 8*(lane>>4), k-half 8*((lane>>3)&1)
    const uint32_t bLd = (uint32_t)((warp_n * 32 + (lane & 7) + 8 * (lane >> 4)) * PITCH_B
                                    + ((lane >> 3) & 1) * 16);

    for (int kc = 0; kc < NC; kc++) {
        CP_WAIT0();
        __syncthreads();
        if (kc + 1 < NC) {
            uint32_t so = (uint32_t)(((kc + 1) & 1) * STAGE_B);
            const int k0 = (kc + 1) * BKH;
#pragma unroll
            for (int j = 0; j < 4; j++) {
                cp16z(aDst[j] + so, aSrc[j] + k0, aSz[j]);
                cp16 (bDst[j] + so, bSrc[j] + k0);
            }
            CP_COMMIT();
        }
        const uint32_t aStage = smb + (kc & 1) * STAGE_B;
        const uint32_t bStage = aStage + OP_BYTES;

#pragma unroll
        for (int s = 0; s < 4; s++) {               // four k16 steps (s*32 bytes)
            uint32_t afr[4][4];
#pragma unroll
            for (int mt = 0; mt < 4; mt++)
                ldm_x4(afr[mt], aStage + aLd + mt * 16 * PITCH_B + s * 32);
            uint32_t bfr[2][4];
#pragma unroll
            for (int p = 0; p < 2; p++)
                ldm_x4(bfr[p], bStage + bLd + p * 16 * PITCH_B + s * 32);
#pragma unroll
            for (int mt = 0; mt < 4; mt++) {
                mma_f16(acc[mt][0], afr[mt], bfr[0]);
                mma_f16(acc[mt][1], afr[mt], bfr[0] + 2);
                mma_f16(acc[mt][2], afr[mt], bfr[1]);
                mma_f16(acc[mt][3], afr[mt], bfr[1] + 2);
            }
        }
    }

    // epilogue: bias + (gelu->half | fp32) + masked scatter
#pragma unroll
    for (int mt = 0; mt < 4; mt++) {
        const int rb = warp_m * 64 + mt * 16 + lr;
#pragma unroll
        for (int half_i = 0; half_i < 2; half_i++) {
            int r    = rb + half_i * 8;
            int slot = sSlot[r];
            if (slot < 0) continue;
#pragma unroll
            for (int nt = 0; nt < 4; nt++) {
                int cidx = warp_n * 32 + nt * 8 + 2 * lc;
                float v0 = acc[mt][nt][half_i * 2 + 0] + sBias[cidx];
                float v1 = acc[mt][nt][half_i * 2 + 1] + sBias[cidx + 1];
                if (FIRST) {
                    __half2 hv = __floats2half2_rn(gelu_erf(v0), gelu_erf(v1));
                    *(__half2*)(g_hh + (size_t)slot * NDIM + jn0 + cidx) = hv;
                } else {
                    float2 w; w.x = v0; w.y = v1;
                    *(float2*)(g_y + (size_t)slot * NDIM + jn0 + cidx) = w;
                }
            }
        }
    }
}

// ---------------------------------------------------------------------------
__global__ void reduce_kernel(float* __restrict__ out) {
    int i = blockIdx.x * blockDim.x + threadIdx.x;
    if (i >= T_ * (E_ / 4)) return;
    int t  = i / (E_ / 4);
    int e4 = i - t * (E_ / 4);
    float4 a = ((const float4*)(g_y + (size_t)(2 * t)     * E_))[e4];
    float4 b = ((const float4*)(g_y + (size_t)(2 * t + 1) * E_))[e4];
    float4 r;
    r.x = 0.5f * (a.x + b.x); r.y = 0.5f * (a.y + b.y);
    r.z = 0.5f * (a.z + b.z); r.w = 0.5f * (a.w + b.w);
    ((float4*)out)[i] = r;
}

// ---------------------------------------------------------------------------
extern "C" void kernel_launch(void* const* d_in, const int* in_sizes, int n_in,
                              void* d_out, int out_size) {
    const float* x  = (const float*)d_in[0];
    const float* Wr = (const float*)d_in[1];
    const float* br = (const float*)d_in[2];
    const float* W1 = (const float*)d_in[3];
    const float* b1 = (const float*)d_in[4];
    const float* W2 = (const float*)d_in[5];
    const float* b2 = (const float*)d_in[6];
    float* out = (float*)d_out;

    float* idx_out = (out_size >= (int)((size_t)T_ * E_ + T_ * K_))
                         ? out + (size_t)T_ * E_ : nullptr;

    static __half* w1t_arg = nullptr;
    static __half* w2t_arg = nullptr;
    if (!w1t_arg) {
        cudaGetSymbolAddress((void**)&w1t_arg, g_W1T);
        cudaGetSymbolAddress((void**)&w2t_arg, g_W2T);
        cudaFuncSetAttribute(expert_gemm_h<E_, H_, true>,
                             cudaFuncAttributeMaxDynamicSharedMemorySize, GEMM_SMEM);
        cudaFuncSetAttribute(expert_gemm_h<H_, E_, false>,
                             cudaFuncAttributeMaxDynamicSharedMemorySize, GEMM_SMEM);
    }

    reset_kernel<<<1, 32>>>();
    router_kernel<<<T_ / 8, 256>>>(x, Wr, br, idx_out);

    cvt_x_kernel<<<T_ * E_ / 4 / 256, 256>>>(x);
    // W1 [E][H] -> [H][E] fp16
    transpose_cvt_kernel<<<dim3(H_ / 32, E_ / 32, X_), dim3(32, 8)>>>(W1, w1t_arg, E_, H_);
    // W2 [H][E] -> [E][H] fp16
    transpose_cvt_kernel<<<dim3(E_ / 32, H_ / 32, X_), dim3(32, 8)>>>(W2, w2t_arg, H_, E_);

    expert_gemm_h<E_, H_, true ><<<dim3(H_ / 128, T_ / 128, X_), 256, GEMM_SMEM>>>(w1t_arg, b1);
    expert_gemm_h<H_, E_, false><<<dim3(E_ / 128, T_ / 128, X_), 256, GEMM_SMEM>>>(w2t_arg, b2);

    reduce_kernel<<<(T_ * (E_ / 4) + 255) / 256, 256>>>(out);
}

// round 6
// speedup vs baseline: 1.4107x; 1.4107x over previous
#include <cuda_runtime.h>
#include <cuda_fp16.h>
#include <math.h>
#include <stdint.h>

// MoE: B=8, N=1024, E=1024, H=1536, X=8, K=2
#define B_  8
#define N_  1024
#define T_  (B_*N_)      // 8192 tokens
#define E_  1024
#define H_  1536
#define X_  8
#define K_  2
#define TS_ (T_*K_)      // 16384 (token, slot) pairs

// ---- scratch (allocation-free: __device__ globals) ----
__device__ int    g_count[X_];
__device__ int    g_slots[X_ * T_];                      // slot id = t*K + k
__device__ __half g_xh[(size_t)T_ * E_];                 // x in fp16
__device__ __half g_W1T[(size_t)X_ * H_ * E_];           // [x][h][e] fp16 (B n-major)
__device__ __half g_W2T[(size_t)X_ * E_ * H_];           // [x][e][h] fp16
__device__ __half g_hh[(size_t)TS_ * H_];                // post-GELU hidden (fp16)
__device__ float  g_y[(size_t)TS_ * E_];                 // expert output (fp32)

// ============================ helpers =======================================
__device__ __forceinline__ uint32_t smem_u32(const void* p) {
    uint32_t a;
    asm("{ .reg .u64 t; cvta.to.shared.u64 t, %1; cvt.u32.u64 %0, t; }" : "=r"(a) : "l"(p));
    return a;
}
__device__ __forceinline__ void cp16z(uint32_t dst, const void* src, uint32_t sz) {
    asm volatile("cp.async.cg.shared.global [%0], [%1], 16, %2;"
                 :: "r"(dst), "l"(src), "r"(sz) : "memory");
}
__device__ __forceinline__ void cp16(uint32_t dst, const void* src) {
    asm volatile("cp.async.cg.shared.global [%0], [%1], 16;"
                 :: "r"(dst), "l"(src) : "memory");
}
#define CP_COMMIT() asm volatile("cp.async.commit_group;" ::: "memory")
#define CP_WAIT0()  asm volatile("cp.async.wait_group 0;" ::: "memory")
#define CP_WAIT1()  asm volatile("cp.async.wait_group 1;" ::: "memory")

__device__ __forceinline__ void mma_f16(float* c, const uint32_t* a, const uint32_t* b) {
    asm volatile("mma.sync.aligned.m16n8k16.row.col.f32.f16.f16.f32 "
                 "{%0,%1,%2,%3}, {%4,%5,%6,%7}, {%8,%9}, {%0,%1,%2,%3};"
                 : "+f"(c[0]), "+f"(c[1]), "+f"(c[2]), "+f"(c[3])
                 : "r"(a[0]), "r"(a[1]), "r"(a[2]), "r"(a[3]), "r"(b[0]), "r"(b[1]));
}

__device__ __forceinline__ float gelu_erf(float v) {
    return 0.5f * v * (1.0f + erff(v * 0.70710678118654752f));
}

// ---------------------------------------------------------------------------
__global__ void reset_kernel() {
    if (threadIdx.x < X_) g_count[threadIdx.x] = 0;
}

// ---------------------------------------------------------------------------
// Router: one warp per token (top-2 of logits == top-2 of softmax).
__global__ void router_kernel(const float* __restrict__ x,
                              const float* __restrict__ Wr,
                              const float* __restrict__ br,
                              float* __restrict__ out_idx) {
    int gwarp = (blockIdx.x * blockDim.x + threadIdx.x) >> 5;
    int lane  = threadIdx.x & 31;
    if (gwarp >= T_) return;
    const float* xr = x + (size_t)gwarp * E_;

    float acc[X_];
#pragma unroll
    for (int j = 0; j < X_; j++) acc[j] = 0.f;
    for (int e = lane; e < E_; e += 32) {
        float xv = xr[e];
        const float4* w4 = (const float4*)(Wr + (size_t)e * X_);
        float4 w0 = w4[0], w1 = w4[1];
        acc[0] += xv * w0.x; acc[1] += xv * w0.y;
        acc[2] += xv * w0.z; acc[3] += xv * w0.w;
        acc[4] += xv * w1.x; acc[5] += xv * w1.y;
        acc[6] += xv * w1.z; acc[7] += xv * w1.w;
    }
#pragma unroll
    for (int j = 0; j < X_; j++)
#pragma unroll
        for (int off = 16; off > 0; off >>= 1)
            acc[j] += __shfl_down_sync(0xffffffffu, acc[j], off);

    if (lane == 0) {
        float v0 = -3.0e38f, v1 = -3.0e38f;
        int   i0 = 0,        i1 = 0;
#pragma unroll
        for (int j = 0; j < X_; j++) {
            float v = acc[j] + br[j];
            if (v > v0)      { v1 = v0; i1 = i0; v0 = v; i0 = j; }
            else if (v > v1) { v1 = v;  i1 = j; }
        }
        if (out_idx) {
            out_idx[gwarp * K_ + 0] = (float)i0;
            out_idx[gwarp * K_ + 1] = (float)i1;
        }
        int p0 = atomicAdd(&g_count[i0], 1);
        g_slots[i0 * T_ + p0] = gwarp * K_ + 0;
        int p1 = atomicAdd(&g_count[i1], 1);
        g_slots[i1 * T_ + p1] = gwarp * K_ + 1;
    }
}

// ---------------------------------------------------------------------------
// x fp32 -> fp16
__global__ void cvt_x_kernel(const float* __restrict__ x) {
    int i = blockIdx.x * 256 + threadIdx.x;             // over T_*E_/4
    float4 v = ((const float4*)x)[i];
    __half2 h0 = __floats2half2_rn(v.x, v.y);
    __half2 h1 = __floats2half2_rn(v.z, v.w);
    ((__half2*)g_xh)[2 * i]     = h0;
    ((__half2*)g_xh)[2 * i + 1] = h1;
}

// in [R][C] fp32 -> out [C][R] fp16 (transpose + convert), batched over z
__global__ void transpose_cvt_kernel(const float* __restrict__ in,
                                     __half* __restrict__ out, int R, int C) {
    __shared__ float t[32][33];
    size_t base = (size_t)blockIdx.z * R * C;
    in  += base; out += base;
    int c0 = blockIdx.x * 32, r0 = blockIdx.y * 32;
#pragma unroll
    for (int j = 0; j < 32; j += 8)
        t[threadIdx.y + j][threadIdx.x] =
            in[(size_t)(r0 + threadIdx.y + j) * C + c0 + threadIdx.x];
    __syncthreads();
#pragma unroll
    for (int j = 0; j < 32; j += 8)
        out[(size_t)(c0 + threadIdx.y + j) * R + r0 + threadIdx.x] =
            __float2half_rn(t[threadIdx.x][threadIdx.y + j]);
}

// ---------------------------------------------------------------------------
// fp16 mma.sync grouped GEMM: 128x128 tile, BK=64 halves, 3-stage cp.async
// ring (wait_group 1), scalar-LDS fragment loads (R4 layout, pitch 72 halves).
// FIRST: C = gelu(xh[token] @ W1T^T + b1) -> g_hh  (KDIM=E_, NDIM=H_)
// else : C =      g_hh[slot] @ W2T^T + b2 -> g_y   (KDIM=H_, NDIM=E_)
#define BKH      64
#define OP_WORDS (128 * 36)              // one operand per stage, 32-bit words
#define STAGE_B  (2 * OP_WORDS * 4)      // 36864 bytes per stage (A+B)
#define NSTAGE   3
#define GEMM_SMEM (1024 + NSTAGE * STAGE_B)

template<int KDIM, int NDIM, bool FIRST>
__global__ __launch_bounds__(256)
void expert_gemm_h(const __half* __restrict__ WT_all,
                   const float* __restrict__ bias_all) {
    extern __shared__ char smx[];
    int*    sSlot = (int*)smx;                 // 128
    float*  sBias = (float*)(smx + 512);       // 128
    char*   sData = smx + 1024;

    const int z    = blockIdx.z;
    const int cnt  = g_count[z];
    const int row0 = blockIdx.y * 128;
    if (row0 >= cnt) return;
    const int jn0  = blockIdx.x * 128;
    const int tid  = threadIdx.x;
    const int lane = tid & 31;
    const int wid  = tid >> 5;

    if (tid < 128) {
        int r = row0 + tid;
        sSlot[tid] = (r < cnt) ? g_slots[z * T_ + r] : -1;
        sBias[tid] = bias_all[(size_t)z * NDIM + jn0 + tid];
    }
    __syncthreads();

    const __half* Abase = FIRST ? g_xh : g_hh;
    const __half* WT    = WT_all + (size_t)z * NDIM * KDIM;

    const uint32_t smb = smem_u32(sData);

    // cp.async mapping: 4 chunks/thread per operand; chunk c=tid*4+j: row=c>>3, col16=c&7
    const __half* aSrc[4]; const __half* bSrc[4];
    uint32_t aSz[4], aDst[4], bDst[4];
#pragma unroll
    for (int j = 0; j < 4; j++) {
        int c = tid * 4 + j;
        int row = c >> 3, col = c & 7;
        int slot = sSlot[row];
        int arow = 0; uint32_t sz = 0;
        if (slot >= 0) { arow = FIRST ? (slot >> 1) : slot; sz = 16; }
        aSrc[j] = Abase + (size_t)arow * KDIM + col * 8;
        aSz[j]  = sz;
        bSrc[j] = WT + (size_t)(jn0 + row) * KDIM + col * 8;
        uint32_t o = (uint32_t)(row * 144 + col * 16);
        aDst[j] = smb + o;
        bDst[j] = smb + OP_WORDS * 4 + o;
    }

    constexpr int NC = KDIM / BKH;

    // prologue: stages 0 and 1 as separate commit groups
#pragma unroll
    for (int st = 0; st < 2; st++) {
        uint32_t so = (uint32_t)(st * STAGE_B);
        const int k0 = st * BKH;
#pragma unroll
        for (int j = 0; j < 4; j++) {
            cp16z(aDst[j] + so, aSrc[j] + k0, aSz[j]);
            cp16 (bDst[j] + so, bSrc[j] + k0);
        }
        CP_COMMIT();
    }

    float acc[4][4][4];
#pragma unroll
    for (int mt = 0; mt < 4; mt++)
#pragma unroll
        for (int nt = 0; nt < 4; nt++)
#pragma unroll
            for (int q = 0; q < 4; q++) acc[mt][nt][q] = 0.f;

    const int warp_m = wid & 1;      // 2 warps over M (64 rows each)
    const int warp_n = wid >> 1;     // 4 warps over N (32 cols each)
    const int lr = lane >> 2;        // group 0..7
    const int lc = lane & 3;         // 0..3

    // per-thread word-index bases into operand tiles
    int awBase[4], bwBase[4];
#pragma unroll
    for (int mt = 0; mt < 4; mt++)
        awBase[mt] = (warp_m * 64 + mt * 16 + lr) * 36 + lc;
#pragma unroll
    for (int nt = 0; nt < 4; nt++)
        bwBase[nt] = (warp_n * 32 + nt * 8 + lr) * 36 + lc;

    int stage = 0;
    for (int kc = 0; kc < NC; kc++) {
        if (kc + 1 < NC) { CP_WAIT1(); } else { CP_WAIT0(); }
        __syncthreads();

        if (kc + 2 < NC) {
            int st2 = stage + 2; if (st2 >= NSTAGE) st2 -= NSTAGE;
            uint32_t so = (uint32_t)(st2 * STAGE_B);
            const int k0 = (kc + 2) * BKH;
#pragma unroll
            for (int j = 0; j < 4; j++) {
                cp16z(aDst[j] + so, aSrc[j] + k0, aSz[j]);
                cp16 (bDst[j] + so, bSrc[j] + k0);
            }
            CP_COMMIT();
        }

        const uint32_t* As32 = (const uint32_t*)(sData + stage * STAGE_B);
        const uint32_t* Bs32 = As32 + OP_WORDS;

#pragma unroll
        for (int s = 0; s < 4; s++) {               // four k16 steps
            const int sk = s * 8;
            uint32_t afr[4][4];
#pragma unroll
            for (int mt = 0; mt < 4; mt++) {
                int w = awBase[mt] + sk;
                afr[mt][0] = As32[w];
                afr[mt][1] = As32[w + 8 * 36];
                afr[mt][2] = As32[w + 4];
                afr[mt][3] = As32[w + 8 * 36 + 4];
            }
            uint32_t bfr[4][2];
#pragma unroll
            for (int nt = 0; nt < 4; nt++) {
                int w = bwBase[nt] + sk;
                bfr[nt][0] = Bs32[w];
                bfr[nt][1] = Bs32[w + 4];
            }
#pragma unroll
            for (int mt = 0; mt < 4; mt++)
#pragma unroll
                for (int nt = 0; nt < 4; nt++)
                    mma_f16(acc[mt][nt], afr[mt], bfr[nt]);
        }

        stage++; if (stage >= NSTAGE) stage -= NSTAGE;
    }

    // epilogue: bias + (gelu->half | fp32) + masked scatter
#pragma unroll
    for (int mt = 0; mt < 4; mt++) {
        const int rb = warp_m * 64 + mt * 16 + lr;
#pragma unroll
        for (int half_i = 0; half_i < 2; half_i++) {
            int r    = rb + half_i * 8;
            int slot = sSlot[r];
            if (slot < 0) continue;
#pragma unroll
            for (int nt = 0; nt < 4; nt++) {
                int cidx = warp_n * 32 + nt * 8 + 2 * lc;
                float v0 = acc[mt][nt][half_i * 2 + 0] + sBias[cidx];
                float v1 = acc[mt][nt][half_i * 2 + 1] + sBias[cidx + 1];
                if (FIRST) {
                    __half2 hv = __floats2half2_rn(gelu_erf(v0), gelu_erf(v1));
                    *(__half2*)(g_hh + (size_t)slot * NDIM + jn0 + cidx) = hv;
                } else {
                    float2 w; w.x = v0; w.y = v1;
                    *(float2*)(g_y + (size_t)slot * NDIM + jn0 + cidx) = w;
                }
            }
        }
    }
}

// ---------------------------------------------------------------------------
__global__ void reduce_kernel(float* __restrict__ out) {
    int i = blockIdx.x * blockDim.x + threadIdx.x;
    if (i >= T_ * (E_ / 4)) return;
    int t  = i / (E_ / 4);
    int e4 = i - t * (E_ / 4);
    float4 a = ((const float4*)(g_y + (size_t)(2 * t)     * E_))[e4];
    float4 b = ((const float4*)(g_y + (size_t)(2 * t + 1) * E_))[e4];
    float4 r;
    r.x = 0.5f * (a.x + b.x); r.y = 0.5f * (a.y + b.y);
    r.z = 0.5f * (a.z + b.z); r.w = 0.5f * (a.w + b.w);
    ((float4*)out)[i] = r;
}

// ---------------------------------------------------------------------------
extern "C" void kernel_launch(void* const* d_in, const int* in_sizes, int n_in,
                              void* d_out, int out_size) {
    const float* x  = (const float*)d_in[0];
    const float* Wr = (const float*)d_in[1];
    const float* br = (const float*)d_in[2];
    const float* W1 = (const float*)d_in[3];
    const float* b1 = (const float*)d_in[4];
    const float* W2 = (const float*)d_in[5];
    const float* b2 = (const float*)d_in[6];
    float* out = (float*)d_out;

    float* idx_out = (out_size >= (int)((size_t)T_ * E_ + T_ * K_))
                         ? out + (size_t)T_ * E_ : nullptr;

    static __half* w1t_arg = nullptr;
    static __half* w2t_arg = nullptr;
    if (!w1t_arg) {
        cudaGetSymbolAddress((void**)&w1t_arg, g_W1T);
        cudaGetSymbolAddress((void**)&w2t_arg, g_W2T);
        cudaFuncSetAttribute(expert_gemm_h<E_, H_, true>,
                             cudaFuncAttributeMaxDynamicSharedMemorySize, GEMM_SMEM);
        cudaFuncSetAttribute(expert_gemm_h<H_, E_, false>,
                             cudaFuncAttributeMaxDynamicSharedMemorySize, GEMM_SMEM);
    }

    reset_kernel<<<1, 32>>>();
    router_kernel<<<T_ / 8, 256>>>(x, Wr, br, idx_out);

    cvt_x_kernel<<<T_ * E_ / 4 / 256, 256>>>(x);
    // W1 [E][H] -> [H][E] fp16
    transpose_cvt_kernel<<<dim3(H_ / 32, E_ / 32, X_), dim3(32, 8)>>>(W1, w1t_arg, E_, H_);
    // W2 [H][E] -> [E][H] fp16
    transpose_cvt_kernel<<<dim3(E_ / 32, H_ / 32, X_), dim3(32, 8)>>>(W2, w2t_arg, H_, E_);

    expert_gemm_h<E_, H_, true ><<<dim3(H_ / 128, T_ / 128, X_), 256, GEMM_SMEM>>>(w1t_arg, b1);
    expert_gemm_h<H_, E_, false><<<dim3(E_ / 128, T_ / 128, X_), 256, GEMM_SMEM>>>(w2t_arg, b2);

    reduce_kernel<<<(T_ * (E_ / 4) + 255) / 256, 256>>>(out);
}